// round 8
// baseline (speedup 1.0000x reference)
#include <cuda_runtime.h>
#include <cuda_bf16.h>

#define BATCH  64
#define NPTS   1024
#define CHUNKS 16
#define JCH    (NPTS / CHUNKS)      // 64 j per block
#define NJP    (JCH / 2)            // 32 j-pairs
#define TPB    128                  // thread t owns shifts 8t .. 8t+7
#define PADN   1040                 // 1024 u64 + swizzle headroom (max +15)

// Deterministic scratch (no device-side allocation; zero-initialized globals).
__device__ float g_partial[CHUNKS][BATCH][NPTS];  // 4 MB
__device__ float g_min[BATCH];
__device__ int   g_cnt_b[BATCH];
__device__ int   g_cnt_all;

typedef unsigned long long u64;

// ---- packed f32x2 helpers ---------------------------------------------------
__device__ __forceinline__ void upk2(u64 v, float& a, float& b) {
    asm("mov.b64 {%0, %1}, %2;" : "=f"(a), "=f"(b) : "l"(v));
}
__device__ __forceinline__ u64 pk2(float a, float b) {
    u64 r; asm("mov.b64 %0, {%1, %2};" : "=l"(r) : "f"(a), "f"(b)); return r;
}
__device__ __forceinline__ u64 addx2(u64 a, u64 b) {
    u64 r; asm("add.rn.f32x2 %0, %1, %2;" : "=l"(r) : "l"(a), "l"(b)); return r;
}
__device__ __forceinline__ u64 mulx2(u64 a, u64 b) {
    u64 r; asm("mul.rn.f32x2 %0, %1, %2;" : "=l"(r) : "l"(a), "l"(b)); return r;
}
__device__ __forceinline__ u64 fmx2(u64 a, u64 b, u64 c) {
    u64 r; asm("fma.rn.f32x2 %0, %1, %2, %3;" : "=l"(r) : "l"(a), "l"(b), "l"(c)); return r;
}
__device__ __forceinline__ float sqrtapx(float x) {
    float r; asm("sqrt.approx.f32 %0, %1;" : "=f"(r) : "f"(x)); return r;
}

// Swizzle on u64 pair index for lane pattern p = C - 4t:
// phi(p) mod 16 = C + (C>>2) - 5t mod 16; gcd(5,16)=1 -> each u64 bank-pair
// hit exactly twice over 32 lanes -> 2-wavefront optimal LDS.64.
__device__ __forceinline__ int swz(int p) { return p + ((p >> 2) & 15); }

// one distance step: acc += || xp + tpair || for both pair halves
#define DIST_ACC(ACC, TX, TY)                                   \
    {                                                           \
        u64 dx = addx2(xpx, (TX)), dy = addx2(xpy, (TY));       \
        u64 d2 = fmx2(dy, dy, mulx2(dx, dx));                   \
        float lo, hi; upk2(d2, lo, hi);                         \
        ACC += sqrtapx(lo); ACC += sqrtapx(hi);                 \
    }

// ---------------------------------------------------------------------------
// Single fused kernel. Grid (CHUNKS, BATCH), TPB=128.
// Thread t owns shifts 8t..8t+7 and walks the chunk's j values in pairs.
// Negated target stored in 4 swizzled SoA u64-pair arrays (even/odd aligned,
// x/y). Per q: 4 fresh LDS.64 + 2 broadcasts serve 16 distances; shifts
// m=2..7 read a depth-4 register window of previous iterations' loads.
// MUFU (16 sqrt / q, rt8 = 128 cyc) is the designed binding pipe.
// ---------------------------------------------------------------------------
__global__ void __launch_bounds__(TPB, 6)
snake_kernel(const float2* __restrict__ x, const float2* __restrict__ tg,
             float* __restrict__ out)
{
    __shared__ __align__(16) u64 SH[4][PADN];   // 0:TXe 1:TXo 2:TYe 3:TYo
    __shared__ u64 XPX[NJP], XPY[NJP];
    __shared__ float redmin[4];
    __shared__ int lastflag;

    const int b     = blockIdx.y;
    const int chunk = blockIdx.x;
    const int j0    = chunk * JCH;
    const int t     = threadIdx.x;

    const float2* __restrict__ tb = tg + b * NPTS;
    const float2* __restrict__ xb = x  + b * NPTS;

    float* TXe = (float*)SH[0];
    float* TXo = (float*)SH[1];
    float* TYe = (float*)SH[2];
    float* TYo = (float*)SH[3];

    // Fill duplicated (2N) negated target, even- and odd-aligned, swizzled.
    #pragma unroll
    for (int i = t; i < 2 * NPTS; i += TPB) {
        float2 tv = tb[i & (NPTS - 1)];
        float nx = -tv.x, ny = -tv.y;
        int pe = 2 * swz(i >> 1) + (i & 1);
        TXe[pe] = nx;  TYe[pe] = ny;
        int j  = (i + 2 * NPTS - 1) & (2 * NPTS - 1);   // i-1 mod 2N
        int po = 2 * swz(j >> 1) + (j & 1);
        TXo[po] = nx;  TYo[po] = ny;
    }
    #pragma unroll
    for (int i = t; i < NJP; i += TPB) {
        float4 q = *(const float4*)(xb + j0 + 2 * i);   // (xj.x,xj.y,xj1.x,xj1.y)
        XPX[i] = pk2(q.x, q.z);
        XPY[i] = pk2(q.y, q.w);
    }
    __syncthreads();

    const int s0 = 8 * t;                       // first shift owned
    const int P  = ((j0 + NPTS) >> 1) - 4 * t;  // even pair index at q=0 (>= 4)

    float a0=0, a1=0, a2=0, a3=0, a4=0, a5=0, a6=0, a7=0;

    // Preload window.
    int i1 = swz(P - 1), i2 = swz(P - 2), i3 = swz(P - 3), i4 = swz(P - 4);
    u64 ex1 = SH[0][i1], ey1 = SH[2][i1];   // even pair P-1   (m=2)
    u64 ex2 = SH[0][i2], ey2 = SH[2][i2];   // even pair P-2   (m=4)
    u64 ex3 = SH[0][i3], ey3 = SH[2][i3];   // even pair P-3   (m=6)
    u64 ox1 = SH[1][i2], oy1 = SH[3][i2];   // odd pair  P-2   (m=3)
    u64 ox2 = SH[1][i3], oy2 = SH[3][i3];   // odd pair  P-3   (m=5)
    u64 ox3 = SH[1][i4], oy3 = SH[3][i4];   // odd pair  P-4   (m=7)
    int fo = i1;                             // swz(P-1): odd fresh index at q=0

    #pragma unroll 4
    for (int q = 0; q < NJP; ++q) {
        const int fe = swz(P + q);              // one swizzle per q
        u64 bxe = SH[0][fe], bye = SH[2][fe];   // even pair p   (m=0)
        u64 bxo = SH[1][fo], byo = SH[3][fo];   // odd  pair p-1 (m=1)
        u64 xpx = XPX[q],    xpy = XPY[q];      // broadcast

        DIST_ACC(a0, bxe, bye)   // m=0
        DIST_ACC(a1, bxo, byo)   // m=1
        DIST_ACC(a2, ex1, ey1)   // m=2
        DIST_ACC(a3, ox1, oy1)   // m=3
        DIST_ACC(a4, ex2, ey2)   // m=4
        DIST_ACC(a5, ox2, oy2)   // m=5
        DIST_ACC(a6, ex3, ey3)   // m=6
        DIST_ACC(a7, ox3, oy3)   // m=7

        // rotate windows (renamed under unroll)
        ex3 = ex2; ey3 = ey2; ex2 = ex1; ey2 = ey1; ex1 = bxe; ey1 = bye;
        ox3 = ox2; oy3 = oy2; ox2 = ox1; oy2 = oy1; ox1 = bxo; oy1 = byo;
        fo = fe;
    }

    *(float4*)&g_partial[chunk][b][s0]     = make_float4(a0, a1, a2, a3);
    *(float4*)&g_partial[chunk][b][s0 + 4] = make_float4(a4, a5, a6, a7);

    // ---- last block of this batch reduces it --------------------------------
    __threadfence();
    if (t == 0) {
        int old = atomicAdd(&g_cnt_b[b], 1);
        lastflag = (old == CHUNKS - 1);
    }
    __syncthreads();
    if (!lastflag) return;
    __threadfence();                                   // acquire all partials
    if (t == 0) g_cnt_b[b] = 0;                        // reset for next replay

    float mn = 3.4e38f;
    #pragma unroll
    for (int k = 0; k < 8; ++k) {
        int s = t + k * TPB;
        float sum = 0.0f;
        #pragma unroll
        for (int c = 0; c < CHUNKS; ++c)
            sum += __ldcg(&g_partial[c][b][s]);
        mn = fminf(mn, sum);
    }
    #pragma unroll
    for (int o = 16; o > 0; o >>= 1)
        mn = fminf(mn, __shfl_xor_sync(0xFFFFFFFFu, mn, o));
    if ((t & 31) == 0) redmin[t >> 5] = mn;
    __syncthreads();

    if (t == 0) {
        float v = fminf(fminf(redmin[0], redmin[1]),
                        fminf(redmin[2], redmin[3]));
        g_min[b] = v;
        __threadfence();
        int old = atomicAdd(&g_cnt_all, 1);
        if (old == BATCH - 1) {                        // last batch-reducer
            g_cnt_all = 0;                             // reset for next replay
            float s = 0.0f;
            #pragma unroll
            for (int bb = 0; bb < BATCH; ++bb)
                s += __ldcg(&g_min[bb]);
            out[0] = s * (1.0f / (float)(BATCH * NPTS));
        }
    }
}

// ---------------------------------------------------------------------------
extern "C" void kernel_launch(void* const* d_in, const int* in_sizes, int n_in,
                              void* d_out, int out_size)
{
    const float2* x  = (const float2*)d_in[0];
    const float2* tg = (const float2*)d_in[1];
    float* out = (float*)d_out;

    dim3 grid(CHUNKS, BATCH);
    snake_kernel<<<grid, TPB>>>(x, tg, out);
}